// round 2
// baseline (speedup 1.0000x reference)
#include <cuda_runtime.h>
#include <cstdint>

// ---------------------------------------------------------------------------
// microGIF step, N=8192.
//   K1: eps[j] = (1+tanh(t))*exp(-t/tau_s)/tau_s,  t = tss - 1.0   (+ zero flag)
//   K2: I_syn = W @ eps   (one block per row; early-exit if eps == 0 everywhere)
//   K3: per-neuron update + JAX threefry2x32 bernoulli (key = (0,42)),
//       PARTITIONABLE counter mode: bits[i] = x0^x1 of threefry((0,42),(0,i))
// Outputs concatenated: [0:N) lambda, [N:2N) spiked_new, [2N:3N) v_new
// ---------------------------------------------------------------------------

#define NMAX 8192

__device__ float g_eps[NMAX];
__device__ float g_Isyn[NMAX];
__device__ int   g_flag;   // 1 if any eps != 0

// ---------------- K1: eps + nonzero flag (single block) --------------------
__global__ void k_eps(const float* __restrict__ tss,
                      const float* __restrict__ tau_s, int n) {
    __shared__ int s_any;
    if (threadIdx.x == 0) s_any = 0;
    __syncthreads();
    int local = 0;
    for (int i = threadIdx.x; i < n; i += blockDim.x) {
        float t = tss[i] - 1.0f;                    // DELTA_DELAY = 1.0
        float ts = tau_s[i];
        float e = (1.0f + tanhf(t)) * expf(-t / ts) / ts;
        g_eps[i] = e;
        if (e != 0.0f) local = 1;
    }
    if (local) atomicOr(&s_any, 1);
    __syncthreads();
    if (threadIdx.x == 0) g_flag = s_any;
}

// ---------------- K2: matvec, one block per row ----------------------------
__global__ void k_matvec(const float* __restrict__ w, int n) {
    int row = blockIdx.x;
    if (g_flag == 0) {                 // eps identically zero -> I_syn zero
        if (threadIdx.x == 0) g_Isyn[row] = 0.0f;
        return;
    }
    const float4* __restrict__ wr =
        reinterpret_cast<const float4*>(w + (size_t)row * n);
    const float4* __restrict__ ev = reinterpret_cast<const float4*>(g_eps);
    float s = 0.0f;
    int nq = n >> 2;
    for (int k = threadIdx.x; k < nq; k += blockDim.x) {
        float4 a = wr[k];
        float4 b = ev[k];
        s += a.x * b.x + a.y * b.y + a.z * b.z + a.w * b.w;
    }
    #pragma unroll
    for (int o = 16; o > 0; o >>= 1) s += __shfl_down_sync(0xffffffffu, s, o);
    __shared__ float ws[8];
    if ((threadIdx.x & 31) == 0) ws[threadIdx.x >> 5] = s;
    __syncthreads();
    if (threadIdx.x == 0) {
        float t = 0.0f;
        #pragma unroll
        for (int j = 0; j < 8; j++) t += ws[j];
        g_Isyn[row] = t;
    }
}

// ---------------- JAX threefry2x32, partitionable counter mode -------------
// key = (0, 42); per-element counter = (hi=0, lo=i); 32-bit bits = x0 ^ x1.
__device__ __forceinline__ uint32_t rotl32(uint32_t x, int r) {
    return (x << r) | (x >> (32 - r));
}

__device__ __forceinline__ uint32_t jax_bits_partitionable(uint32_t i) {
    const uint32_t k0 = 0u, k1 = 42u;
    const uint32_t k2 = k0 ^ k1 ^ 0x1BD11BDAu;
    uint32_t ks[3] = {k0, k1, k2};
    uint32_t x0 = 0u + k0;   // counter hi word = 0
    uint32_t x1 = i  + k1;   // counter lo word = i
    const int rot[8] = {13, 15, 26, 6, 17, 29, 16, 24};
    #pragma unroll
    for (int it = 0; it < 5; it++) {
        const int* rr = rot + 4 * (it & 1);
        #pragma unroll
        for (int j = 0; j < 4; j++) {
            x0 += x1;
            x1 = rotl32(x1, rr[j]);
            x1 ^= x0;
        }
        x0 += ks[(it + 1) % 3];
        x1 += ks[(it + 2) % 3] + (uint32_t)(it + 1);
    }
    return x0 ^ x1;
}

// ---------------- K3: per-neuron update + bernoulli ------------------------
__global__ void k_update(const float* __restrict__ I_ext,
                         const float* __restrict__ w,
                         const float* __restrict__ v,
                         const float* __restrict__ spiked,
                         const float* __restrict__ tss,
                         const float* __restrict__ theta_v,
                         const float* __restrict__ tau_m,
                         const float* __restrict__ tau_theta,
                         const float* __restrict__ J_theta,
                         const float* __restrict__ E_L,
                         const float* __restrict__ c,
                         const float* __restrict__ Delta_u,
                         const float* __restrict__ theta_inf,
                         float* __restrict__ out, int n) {
    int i = blockIdx.x * blockDim.x + threadIdx.x;
    if (i >= n) return;

    // diagonal mask: subtract w[i][i]*eps[i]
    float Isyn = g_Isyn[i] - w[(size_t)i * n + i] * g_eps[i];

    float th = theta_v[i] +
               (theta_inf[i] - theta_v[i] + J_theta[i] * spiked[i]) / tau_theta[i];
    float v_next = v[i] + (E_L[i] - v[i] + I_ext[i]) / tau_m[i] + Isyn;

    float notref = (tss[i] > 2.0f) ? 1.0f : 0.0f;   // T_REFRACTORY = 2.0
    float lam = notref * c[i] * expf((v_next - th) / Delta_u[i]);
    lam = fminf(fmaxf(lam, 0.0f), 1.0f);

    // jax.random.bernoulli(key(42), lam):  uniform(key, n) < lam
    uint32_t bits = jax_bits_partitionable((uint32_t)i);
    float u = __uint_as_float((bits >> 9) | 0x3F800000u) - 1.0f;
    float sp = (u < lam) ? 1.0f : 0.0f;
    float v_new = (sp != 0.0f) ? 0.0f : v_next;     // RESET_POTENTIAL = 0

    out[i]         = lam;
    out[n + i]     = sp;
    out[2 * n + i] = v_new;
}

extern "C" void kernel_launch(void* const* d_in, const int* in_sizes, int n_in,
                              void* d_out, int out_size) {
    const float* I_ext     = (const float*)d_in[0];
    const float* w         = (const float*)d_in[1];
    const float* v         = (const float*)d_in[2];
    const float* spiked    = (const float*)d_in[3];
    const float* tss       = (const float*)d_in[4];
    const float* theta_v   = (const float*)d_in[5];
    const float* tau_m     = (const float*)d_in[6];
    const float* tau_s     = (const float*)d_in[7];
    const float* tau_theta = (const float*)d_in[8];
    const float* J_theta   = (const float*)d_in[9];
    const float* E_L       = (const float*)d_in[10];
    const float* c         = (const float*)d_in[11];
    const float* Delta_u   = (const float*)d_in[12];
    const float* theta_inf = (const float*)d_in[13];
    float* out = (float*)d_out;

    int n = in_sizes[0];
    if (n > NMAX) n = NMAX;

    k_eps<<<1, 1024>>>(tss, tau_s, n);
    k_matvec<<<n, 256>>>(w, n);
    int blocks = (n + 255) / 256;
    k_update<<<blocks, 256>>>(I_ext, w, v, spiked, tss, theta_v, tau_m,
                              tau_theta, J_theta, E_L, c, Delta_u, theta_inf,
                              out, n);
}